// round 15
// baseline (speedup 1.0000x reference)
#include <cuda_runtime.h>

// XdGate on site INDEX=3 of an L=8 qutrit (D=3) state vector, N = 3^8 = 6561.
//
// U = I x I x I x M x I x I x I x I with M|i> = |(3-i) mod 3> — a pure
// permutation of the site-3 trit (stride 3^4 = 81):
//   t=0 -> delta 0, t=1 -> +81, t=2 -> -81 (element offsets).
//
// KERNEL OF RECORD — 14 completed measurements across the full variant
// lattice: grid {1, 7, 9, 26, 27} x per-thread work {1, 4, 9} x {div,
// div-free trit} x {1D/2D/3D block} x {guard, no-guard}.
// Findings: all multi-CTA variants share one ncu noise cloud (3.97-4.54us,
// +-0.3us — this exact binary measured 4.06/4.16/4.29/4.29/4.35); grid=1 is
// strictly worse (4.83us, single-SM LSU serialization). Harness replay time
// for this binary across five runs: 5.02/5.06/5.63/5.92/5.92us — +-0.5us
// noise around a fixed single-launch floor (~4.2us kernel at unboosted DVFS
// clocks + ~1us replay overhead). DRAM 0.1%, issue <=3%, ALU/FMA ~0%: the
// 52KB permutation and ~10-instruction body cannot register above the floor.
//
// Structure: exact 27x243 cover -> no bounds guard, no tail; branchless
// delta; one scalar gather per thread; regs=16, smem=0.
// Ruled out with evidence: 16B vectorization (src/dst differ by 81 elems
// = 4B mod 16 -> cannot co-align), memcpy decomposition (>=3 graph nodes
// vs 1 kernel node), TMA/smem staging (adds fixed cost), grid=1 persistent
// form (measured regression).

static constexpr int STRIDE = 81;   // 3^4

__global__ __launch_bounds__(243) void xd_gate_kernel(
    const float* __restrict__ x, float* __restrict__ out) {
    int idx = blockIdx.x * 243 + threadIdx.x;   // exact cover of [0, 6561)

    int t = (idx / STRIDE) % 3;
    // delta multiplier: t=0 -> 0, t=1 -> +1, t=2 -> -1
    int d = (t == 1) - (t == 2);
    out[idx] = x[idx + d * STRIDE];
}

extern "C" void kernel_launch(void* const* d_in, const int* in_sizes, int n_in,
                              void* d_out, int out_size) {
    const float* x = (const float*)d_in[0];   // [6561, 1] float32
    // d_in[1] is M [3,3] — permutation baked in.
    float* out = (float*)d_out;

    xd_gate_kernel<<<27, 243>>>(x, out);      // 27 * 243 = 6561 exactly
}

// round 16
// speedup vs baseline: 1.1635x; 1.1635x over previous
#include <cuda_runtime.h>

// XdGate on site INDEX=3 of an L=8 qutrit (D=3) state vector, N = 3^8 = 6561.
//
// U = I x I x I x M x I x I x I x I with M|i> = |(3-i) mod 3> — a pure
// permutation of the site-3 trit (stride 3^4 = 81):
//   t=0 -> delta 0, t=1 -> +81, t=2 -> -81 (element offsets).
//
// KERNEL OF RECORD — 15 completed measurements across the full variant
// lattice: grid {1, 7, 9, 26, 27} x per-thread work {1, 4, 9} x {div,
// div-free trit} x {1D/2D/3D block} x {guard, no-guard}.
// Findings: all multi-CTA variants share one ncu noise cloud (3.97-4.54us;
// this binary: 4.06/4.16/4.16/4.29/4.29/4.35); grid=1 strictly worse
// (4.83us, single-SM LSU serialization). Harness replay time for this
// binary across six runs: 5.02/5.06/5.63/5.92/5.92/5.92us — bimodal
// (likely DVFS state of the replay loop: boosted ~5.0, unboosted ~5.9),
// not controllable from a deterministic captured kernel. DRAM 0.1%,
// issue <=3%, ALU/FMA ~0%: the 52KB permutation and ~10-instruction body
// cannot register above the fixed single-launch floor.
//
// Structure: exact 27x243 cover -> no bounds guard, no tail; branchless
// delta; one scalar gather per thread; regs=16, smem=0.
// Ruled out with evidence: 16B vectorization (src/dst differ by 81 elems
// = 4B mod 16 -> cannot co-align), memcpy2D decomposition (3 pitched-copy
// graph nodes, each with per-node replay cost vs this single node),
// TMA/smem staging (adds fixed cost), grid=1 persistent form (measured
// regression).

static constexpr int STRIDE = 81;   // 3^4

__global__ __launch_bounds__(243) void xd_gate_kernel(
    const float* __restrict__ x, float* __restrict__ out) {
    int idx = blockIdx.x * 243 + threadIdx.x;   // exact cover of [0, 6561)

    int t = (idx / STRIDE) % 3;
    // delta multiplier: t=0 -> 0, t=1 -> +1, t=2 -> -1
    int d = (t == 1) - (t == 2);
    out[idx] = x[idx + d * STRIDE];
}

extern "C" void kernel_launch(void* const* d_in, const int* in_sizes, int n_in,
                              void* d_out, int out_size) {
    const float* x = (const float*)d_in[0];   // [6561, 1] float32
    // d_in[1] is M [3,3] — permutation baked in.
    float* out = (float*)d_out;

    xd_gate_kernel<<<27, 243>>>(x, out);      // 27 * 243 = 6561 exactly
}